// round 2
// baseline (speedup 1.0000x reference)
#include <cuda_runtime.h>
#include <cuda_bf16.h>
#include <cstdint>

// Problem constants (fixed shapes for this problem)
#define NN 524288   // nodes
#define DD 256      // input dim
#define HH 128      // hidden dim
#define BB 2048     // segments

// ---------------- scratch (device globals; no allocation allowed) ----------
__device__ float g_scores[NN];
__device__ float g_segmax[BB];
__device__ float g_segsum[BB];

// ---------------- helpers ---------------------------------------------------
__device__ __forceinline__ uint32_t f2tf32(float f) {
    uint32_t u;
    asm("cvt.rna.tf32.f32 %0, %1;" : "=r"(u) : "f"(f));
    return u;
}

__device__ __forceinline__ void mma_tf32(float& c0, float& c1, float& c2, float& c3,
                                         uint32_t a0, uint32_t a1, uint32_t a2, uint32_t a3,
                                         uint32_t b0, uint32_t b1) {
    asm("mma.sync.aligned.m16n8k8.row.col.f32.tf32.tf32.f32 "
        "{%0,%1,%2,%3}, {%4,%5,%6,%7}, {%8,%9}, {%0,%1,%2,%3};"
        : "+f"(c0), "+f"(c1), "+f"(c2), "+f"(c3)
        : "r"(a0), "r"(a1), "r"(a2), "r"(a3), "r"(b0), "r"(b1));
}

// ---------------- kernel A: scores = tanh(x@W1 + b1) @ W2 + b2 -------------
// CTA: 256 threads (8 warps). CTA tile: 128 nodes x 128 cols, K = 256.
// W1 in smem as tf32, row stride 136 (conflict-free B-frag loads).
// x chunk (128 nodes x 32 k) transposed in smem, row stride 137, double buffer.
#define W1_STRIDE 136
#define XT_STRIDE 137
#define KC 32
#define XBUF_U32 (KC * XT_STRIDE)            // 4384
#define W1_U32   (DD * W1_STRIDE)            // 34816
#define SMEM_A_U32 (W1_U32 + 2 * XBUF_U32 + 256)
#define SMEM_A_BYTES (SMEM_A_U32 * 4)

__global__ void __launch_bounds__(256, 1)
scores_kernel(const float* __restrict__ x,
              const float* __restrict__ W1,
              const float* __restrict__ b1,
              const float* __restrict__ W2,
              const float* __restrict__ b2) {
    extern __shared__ uint32_t sm[];
    uint32_t* w1s = sm;                        // [256][136] tf32
    uint32_t* xs  = sm + W1_U32;               // [2][32][137] tf32
    float*    b1s = (float*)(sm + W1_U32 + 2 * XBUF_U32);  // [128]
    float*    w2s = b1s + 128;                               // [128]

    const int tid  = threadIdx.x;
    const int lane = tid & 31;
    const int wid  = tid >> 5;
    const int t    = lane & 3;     // thread-in-group
    const int g    = lane >> 2;    // group id
    const int n0   = blockIdx.x * 128;
    const int wn   = wid * 16;     // warp node base within tile

    // ---- stage W1 (tf32) into smem: float4 loads, uint4 stores ----
    const float4* w14 = (const float4*)W1;
    #pragma unroll
    for (int it = 0; it < 32; ++it) {
        int i = tid + it * 256;            // 8192 float4 total
        int k = i >> 5, q = i & 31;
        float4 v = w14[i];
        uint4 u;
        u.x = f2tf32(v.x); u.y = f2tf32(v.y); u.z = f2tf32(v.z); u.w = f2tf32(v.w);
        *((uint4*)(w1s + k * W1_STRIDE + 4 * q)) = u;
    }
    if (tid < 128) { b1s[tid] = b1[tid]; w2s[tid] = W2[tid]; }

    // ---- accumulators: 16 n-atoms x 4 regs ----
    float acc[16][4];
    #pragma unroll
    for (int a = 0; a < 16; ++a) {
        #pragma unroll
        for (int r = 0; r < 4; ++r) acc[a][r] = 0.0f;
    }

    // ---- prefetch chunk 0 ----
    const float4* x4 = (const float4*)x;
    float4 rx[4];
    #pragma unroll
    for (int tt = 0; tt < 4; ++tt) {
        int id = tid + tt * 256;
        int node = id >> 3, q = id & 7;
        rx[tt] = x4[(size_t)(n0 + node) * 64 + q];   // chunk 0: ch*8 + q
    }

    for (int ch = 0; ch < 8; ++ch) {
        uint32_t* xb = xs + (ch & 1) * XBUF_U32;
        // store staged chunk (transposed, conflict-free via stride 137)
        #pragma unroll
        for (int tt = 0; tt < 4; ++tt) {
            int id = tid + tt * 256;
            int node = id >> 3, q = id & 7;
            uint32_t* p = xb + node;
            p[(4 * q + 0) * XT_STRIDE] = f2tf32(rx[tt].x);
            p[(4 * q + 1) * XT_STRIDE] = f2tf32(rx[tt].y);
            p[(4 * q + 2) * XT_STRIDE] = f2tf32(rx[tt].z);
            p[(4 * q + 3) * XT_STRIDE] = f2tf32(rx[tt].w);
        }
        __syncthreads();
        // prefetch next chunk
        if (ch < 7) {
            #pragma unroll
            for (int tt = 0; tt < 4; ++tt) {
                int id = tid + tt * 256;
                int node = id >> 3, q = id & 7;
                rx[tt] = x4[(size_t)(n0 + node) * 64 + (ch + 1) * 8 + q];
            }
        }
        // compute 4 k-steps of this chunk
        #pragma unroll
        for (int ks = 0; ks < 4; ++ks) {
            int kl = ks * 8;
            uint32_t a0 = xb[(kl + t) * XT_STRIDE + wn + g];
            uint32_t a1 = xb[(kl + t) * XT_STRIDE + wn + g + 8];
            uint32_t a2 = xb[(kl + t + 4) * XT_STRIDE + wn + g];
            uint32_t a3 = xb[(kl + t + 4) * XT_STRIDE + wn + g + 8];
            const uint32_t* wr0 = w1s + (ch * KC + kl + t) * W1_STRIDE;
            const uint32_t* wr1 = wr0 + 4 * W1_STRIDE;
            #pragma unroll
            for (int a = 0; a < 16; ++a) {
                uint32_t b0 = wr0[a * 8 + g];
                uint32_t b1v = wr1[a * 8 + g];
                mma_tf32(acc[a][0], acc[a][1], acc[a][2], acc[a][3],
                         a0, a1, a2, a3, b0, b1v);
            }
        }
        __syncthreads();
    }

    // ---- epilogue: +b1, tanh, dot W2, reduce, +b2 ----
    float p0 = 0.0f, p1 = 0.0f;
    #pragma unroll
    for (int a = 0; a < 16; ++a) {
        #pragma unroll
        for (int rr = 0; rr < 2; ++rr) {
            int cc = a * 8 + 2 * t + rr;
            float bb = b1s[cc], ww = w2s[cc];
            p0 += tanhf(acc[a][rr]     + bb) * ww;   // row g
            p1 += tanhf(acc[a][2 + rr] + bb) * ww;   // row g+8
        }
    }
    p0 += __shfl_xor_sync(0xffffffffu, p0, 1);
    p0 += __shfl_xor_sync(0xffffffffu, p0, 2);
    p1 += __shfl_xor_sync(0xffffffffu, p1, 1);
    p1 += __shfl_xor_sync(0xffffffffu, p1, 2);
    if (t == 0) {
        float bb2 = b2[0];
        int node = n0 + wn + g;
        g_scores[node]     = p0 + bb2;
        g_scores[node + 8] = p1 + bb2;
    }
}

// ---------------- binary search: first i with batch[i] >= v ----------------
__device__ __forceinline__ int lower_bound_i32(const int* __restrict__ a, int n, int v) {
    int lo = 0, hi = n;
    while (lo < hi) {
        int mid = (lo + hi) >> 1;
        if (a[mid] < v) lo = mid + 1; else hi = mid;
    }
    return lo;
}

// ---------------- kernel B: per-segment max + sum(exp) ---------------------
__global__ void segstats_kernel(const int* __restrict__ batch) {
    const int b = blockIdx.x;
    const int tid = threadIdx.x;
    __shared__ int se[2];
    __shared__ float red[256];

    if (tid == 0) {
        se[0] = lower_bound_i32(batch, NN, b);
        se[1] = lower_bound_i32(batch, NN, b + 1);
    }
    __syncthreads();
    const int st = se[0], en = se[1];

    // max
    float m = -1e30f;
    for (int i = st + tid; i < en; i += 256) m = fmaxf(m, g_scores[i]);
    red[tid] = m;
    __syncthreads();
    #pragma unroll
    for (int off = 128; off > 0; off >>= 1) {
        if (tid < off) red[tid] = fmaxf(red[tid], red[tid + off]);
        __syncthreads();
    }
    m = red[0];
    __syncthreads();

    // sum exp
    float z = 0.0f;
    for (int i = st + tid; i < en; i += 256) z += expf(g_scores[i] - m);
    red[tid] = z;
    __syncthreads();
    #pragma unroll
    for (int off = 128; off > 0; off >>= 1) {
        if (tid < off) red[tid] += red[tid + off];
        __syncthreads();
    }
    if (tid == 0) {
        if (en > st) { g_segmax[b] = m; g_segsum[b] = red[0]; }
        else         { g_segmax[b] = 0.0f; g_segsum[b] = 0.0f; }
    }
}

// ---------------- kernel C: pooled[b,d] = sum_i x[i,d] * w_i ----------------
__global__ void pool_kernel(const float* __restrict__ x,
                            const int* __restrict__ batch,
                            float* __restrict__ out) {
    const int b = blockIdx.x;
    const int tid = threadIdx.x;   // = dim d (0..255)
    __shared__ int se[2];
    __shared__ float ws[256];

    if (tid == 0) {
        se[0] = lower_bound_i32(batch, NN, b);
        se[1] = lower_bound_i32(batch, NN, b + 1);
    }
    __syncthreads();
    const int st = se[0], en = se[1];
    const float m = g_segmax[b];
    const float Z = g_segsum[b];
    const float invZ = (en > st && Z > 0.0f) ? (1.0f / Z) : 0.0f;

    float acc = 0.0f;
    for (int i0 = st; i0 < en; i0 += 256) {
        int cnt = min(256, en - i0);
        __syncthreads();
        if (tid < cnt) ws[tid] = expf(g_scores[i0 + tid] - m) * invZ;
        __syncthreads();
        const float* xp = x + (size_t)i0 * DD + tid;
        int j = 0;
        for (; j + 8 <= cnt; j += 8) {
            float v0 = xp[(size_t)(j + 0) * DD];
            float v1 = xp[(size_t)(j + 1) * DD];
            float v2 = xp[(size_t)(j + 2) * DD];
            float v3 = xp[(size_t)(j + 3) * DD];
            float v4 = xp[(size_t)(j + 4) * DD];
            float v5 = xp[(size_t)(j + 5) * DD];
            float v6 = xp[(size_t)(j + 6) * DD];
            float v7 = xp[(size_t)(j + 7) * DD];
            acc += v0 * ws[j + 0]; acc += v1 * ws[j + 1];
            acc += v2 * ws[j + 2]; acc += v3 * ws[j + 3];
            acc += v4 * ws[j + 4]; acc += v5 * ws[j + 5];
            acc += v6 * ws[j + 6]; acc += v7 * ws[j + 7];
        }
        for (; j < cnt; ++j) acc += xp[(size_t)j * DD] * ws[j];
    }
    out[(size_t)b * DD + tid] = acc;
}

// ---------------- launch -----------------------------------------------------
extern "C" void kernel_launch(void* const* d_in, const int* in_sizes, int n_in,
                              void* d_out, int out_size) {
    (void)in_sizes; (void)n_in; (void)out_size;
    const float* x     = (const float*)d_in[0];
    const int*   batch = (const int*)d_in[1];
    const float* W1    = (const float*)d_in[2];
    const float* b1    = (const float*)d_in[3];
    const float* W2    = (const float*)d_in[4];
    const float* b2    = (const float*)d_in[5];
    float*       out   = (float*)d_out;

    cudaFuncSetAttribute(scores_kernel,
                         cudaFuncAttributeMaxDynamicSharedMemorySize,
                         SMEM_A_BYTES);

    scores_kernel<<<NN / 128, 256, SMEM_A_BYTES>>>(x, W1, b1, W2, b2);
    segstats_kernel<<<BB, 256>>>(batch);
    pool_kernel<<<BB, 256>>>(x, batch, out);
}